// round 4
// baseline (speedup 1.0000x reference)
#include <cuda_runtime.h>
#include <cuda_bf16.h>
#include <math.h>
#include <stdint.h>

#define B_ 8
#define N_ 4096
#define C_ 768
#define H_ 8
#define HD 96
#define M_ (B_*N_)        // 32768 rows
#define QKV_COLS (3*C_)   // 2304
#define KDIM 768
#define KSTAGES 24        // 768 / 32

// ---------------- scratch (device globals: allocation-free) ----------------
__device__ __align__(128) float g_qkv[(size_t)M_ * QKV_COLS];   // [M, 3C]
__device__ __align__(128) float g_ctx[(size_t)M_ * C_];         // [M, C]
__device__ __align__(128) float g_S[B_ * H_ * HD * HD];         // logits/attn
__device__ __align__(128) float g_rn[B_ * 2 * C_];              // 1/max(||col||,eps)
__device__ __align__(128) __nv_bfloat16 g_Bpk1[(size_t)18 * KSTAGES * 8192];  // Wqkv hi/lo
__device__ __align__(128) __nv_bfloat16 g_Bpk2[(size_t)6  * KSTAGES * 8192];  // Wproj hi/lo
__device__ __align__(128) __nv_bfloat16 g_Apk1[(size_t)256 * KSTAGES * 8192]; // x hi/lo
__device__ __align__(128) __nv_bfloat16 g_Apk2[(size_t)256 * KSTAGES * 8192]; // ctx hi/lo

// ---------------- PTX helpers ----------------------------------------------
__device__ __forceinline__ uint32_t smem_u32(const void* p) {
    uint32_t a;
    asm("{ .reg .u64 t; cvta.to.shared.u64 t, %1; cvt.u32.u64 %0, t; }" : "=r"(a) : "l"(p));
    return a;
}

#define LDSM4(r0, r1, r2, r3, addr) \
    asm volatile("ldmatrix.sync.aligned.m8n8.x4.shared.b16 {%0,%1,%2,%3}, [%4];" \
                 : "=r"(r0), "=r"(r1), "=r"(r2), "=r"(r3) : "r"(addr))

#define MMA16816(c, a, b0, b1) \
    asm volatile("mma.sync.aligned.m16n8k16.row.col.f32.bf16.bf16.f32 " \
                 "{%0,%1,%2,%3}, {%4,%5,%6,%7}, {%8,%9}, {%0,%1,%2,%3};" \
                 : "+f"((c)[0]), "+f"((c)[1]), "+f"((c)[2]), "+f"((c)[3]) \
                 : "r"((a)[0]), "r"((a)[1]), "r"((a)[2]), "r"((a)[3]), \
                   "r"(b0), "r"(b1))

#define CP_ASYNC16(dst, src) \
    asm volatile("cp.async.cg.shared.global [%0], [%1], 16;" \
                 :: "r"(dst), "l"(src) : "memory")
#define CP_COMMIT() asm volatile("cp.async.commit_group;" ::: "memory")
#define CP_WAIT1()  asm volatile("cp.async.wait_group 1;" ::: "memory")

// ---------------- weight prepack: W[K,N] -> bf16 hi/lo [n][k] tiles --------
// per (ntile, kstage) block of 8192 bf16: [hi 128x32][lo 128x32], 64B rows
__global__ void prepack_kernel(const float* __restrict__ W,
                               __nv_bfloat16* __restrict__ pack, int Ncols)
{
    int id = blockIdx.x * 256 + threadIdx.x;
    int n = id % Ncols, k = id / Ncols;
    float w = W[id];
    __nv_bfloat16 h = __float2bfloat16_rn(w);
    __nv_bfloat16 lo = __float2bfloat16_rn(w - __bfloat162float(h));
    int nt = n >> 7, nl = n & 127, st = k >> 5, kl = k & 31;
    size_t base = ((size_t)nt * KSTAGES + st) * 8192 + (size_t)nl * 32 + kl;
    pack[base] = h;
    pack[base + 4096] = lo;
}

// ---------------- A split: fp32 [M,768] -> bf16 hi/lo packed tiles ----------
// MODE 0: src = param (x) -> g_Apk1.   MODE 1: src = g_ctx -> g_Apk2.
template<int MODE>
__global__ void asplit_kernel(const float* __restrict__ Ap)
{
    const float* A = MODE ? (const float*)g_ctx : Ap;
    __nv_bfloat16* pack = MODE ? g_Apk2 : g_Apk1;
    int id = blockIdx.x * 256 + threadIdx.x;       // one float4 per thread
    int m = id / (KDIM / 4);
    int k = (id % (KDIM / 4)) * 4;
    float4 v = *(const float4*)(A + (size_t)id * 4);
    __nv_bfloat16 hx = __float2bfloat16_rn(v.x);
    __nv_bfloat16 hy = __float2bfloat16_rn(v.y);
    __nv_bfloat16 hz = __float2bfloat16_rn(v.z);
    __nv_bfloat16 hw = __float2bfloat16_rn(v.w);
    __nv_bfloat162 h0; h0.x = hx; h0.y = hy;
    __nv_bfloat162 h1; h1.x = hz; h1.y = hw;
    __nv_bfloat162 l0, l1;
    l0.x = __float2bfloat16_rn(v.x - __bfloat162float(hx));
    l0.y = __float2bfloat16_rn(v.y - __bfloat162float(hy));
    l1.x = __float2bfloat16_rn(v.z - __bfloat162float(hz));
    l1.y = __float2bfloat16_rn(v.w - __bfloat162float(hw));
    int mt = m >> 7, r = m & 127, st = k >> 5, kl = k & 31;
    size_t base = ((size_t)mt * KSTAGES + st) * 8192 + (size_t)r * 32 + kl;
    *(__nv_bfloat162*)(pack + base)            = h0;
    *(__nv_bfloat162*)(pack + base + 2)        = h1;
    *(__nv_bfloat162*)(pack + base + 4096)     = l0;
    *(__nv_bfloat162*)(pack + base + 4096 + 2) = l1;
}

// ---------------- bf16 split-3 GEMM: 128x128x32 tile, mma.sync -------------
// SMEM per buffer (pitch 80B): Ahi@0 Alo@10240 Bhi@20480 Blo@30720
#define BUF_BYTES 40960
#define GEMM_DSMEM (2 * BUF_BYTES + 128)

// AMODE: 0 -> g_Apk1 (x), 1 -> g_Apk2 (ctx). CMODE: 1 -> g_qkv, 0 -> param.
template<int AMODE, int CMODE>
__global__ void __launch_bounds__(256, 1)
gemm_bf16_kernel(const __nv_bfloat16* __restrict__ Bpack,
                 float* __restrict__ Cp, const float* __restrict__ bias, int ldc)
{
    const __nv_bfloat16* Apack = AMODE ? g_Apk2 : g_Apk1;
    float* C = CMODE ? (float*)g_qkv : Cp;

    extern __shared__ char dsm[];
    const int tid = threadIdx.x, wid = tid >> 5, lane = tid & 31;
    const int wm = wid >> 2, wn = wid & 3;          // 2 x 4 warp grid
    const int m0 = blockIdx.y * 128, bx = blockIdx.x;

    uint32_t dyn0 = smem_u32(dsm);
    uint32_t tile0 = (dyn0 + 127) & ~127u;

    // ldmatrix per-lane addressing
    const uint32_t ld_row = lane & 15;
    const uint32_t ld_k8b = ((lane >> 4) * 8) * 2;  // byte offset of k half
    const uint32_t a_off = (wm * 64 + ld_row) * 80 + ld_k8b;
    const uint32_t b_off = (wn * 32 + ld_row) * 80 + ld_k8b;

    float c[4][4][4];
#pragma unroll
    for (int i = 0; i < 4; i++)
#pragma unroll
        for (int j = 0; j < 4; j++)
#pragma unroll
            for (int q = 0; q < 4; q++) c[i][j][q] = 0.f;

    const char* asrc_base = (const char*)Apack + (size_t)blockIdx.y * KSTAGES * 16384;
    const char* bsrc_base = (const char*)Bpack + (size_t)bx * KSTAGES * 16384;

    // per-thread: 4 x 16B chunks for A + 4 for B per stage
    auto cp_stage = [&](int st, uint32_t bufb) {
        const char* asrc = asrc_base + (size_t)st * 16384;
        const char* bsrc = bsrc_base + (size_t)st * 16384;
#pragma unroll
        for (int l = 0; l < 4; l++) {
            int fid = tid + 256 * l;
            int half = fid >> 9, rem = fid & 511, row = rem >> 2, cc = rem & 3;
            uint32_t doff = half * 10240 + row * 80 + cc * 16;
            uint32_t soff = half * 8192 + row * 64 + cc * 16;
            CP_ASYNC16(tile0 + bufb + doff, asrc + soff);
            CP_ASYNC16(tile0 + bufb + 20480 + doff, bsrc + soff);
        }
    };

    // prologue
    cp_stage(0, 0); CP_COMMIT();

    for (int st = 0; st < KSTAGES; st++) {
        const uint32_t bufb = (st & 1) * BUF_BYTES;
        if (st + 1 < KSTAGES) cp_stage(st + 1, BUF_BYTES - bufb);
        CP_COMMIT();
        CP_WAIT1();
        __syncthreads();

        // compute on bufb
        const uint32_t aP = tile0 + bufb;
        const uint32_t bP = aP + 20480;
        uint32_t af[4][4], bh[8], bl[8];
#pragma unroll
        for (int ks = 0; ks < 2; ks++) {
            const uint32_t ko = ks * 32;             // 16 k * 2B
            // A hi frags
#pragma unroll
            for (int mt = 0; mt < 4; mt++)
                LDSM4(af[mt][0], af[mt][1], af[mt][2], af[mt][3],
                      aP + a_off + mt * 1280 + ko);
            // B hi frags (n 0-15, n 16-31)
            LDSM4(bh[0], bh[1], bh[2], bh[3], bP + b_off + ko);
            LDSM4(bh[4], bh[5], bh[6], bh[7], bP + b_off + 1280 + ko);
#pragma unroll
            for (int mt = 0; mt < 4; mt++) {
                MMA16816(c[mt][0], af[mt], bh[0], bh[2]);
                MMA16816(c[mt][1], af[mt], bh[1], bh[3]);
                MMA16816(c[mt][2], af[mt], bh[4], bh[6]);
                MMA16816(c[mt][3], af[mt], bh[5], bh[7]);
            }
            // B lo frags
            LDSM4(bl[0], bl[1], bl[2], bl[3], bP + 10240 + b_off + ko);
            LDSM4(bl[4], bl[5], bl[6], bl[7], bP + 10240 + b_off + 1280 + ko);
#pragma unroll
            for (int mt = 0; mt < 4; mt++) {
                MMA16816(c[mt][0], af[mt], bl[0], bl[2]);
                MMA16816(c[mt][1], af[mt], bl[1], bl[3]);
                MMA16816(c[mt][2], af[mt], bl[4], bl[6]);
                MMA16816(c[mt][3], af[mt], bl[5], bl[7]);
            }
            // A lo frags (reuse af)
#pragma unroll
            for (int mt = 0; mt < 4; mt++)
                LDSM4(af[mt][0], af[mt][1], af[mt][2], af[mt][3],
                      aP + 10240 + a_off + mt * 1280 + ko);
#pragma unroll
            for (int mt = 0; mt < 4; mt++) {
                MMA16816(c[mt][0], af[mt], bh[0], bh[2]);
                MMA16816(c[mt][1], af[mt], bh[1], bh[3]);
                MMA16816(c[mt][2], af[mt], bh[4], bh[6]);
                MMA16816(c[mt][3], af[mt], bh[5], bh[7]);
            }
        }
        __syncthreads();
    }

    // epilogue
    const int g = lane >> 2, tg = lane & 3;
#pragma unroll
    for (int mt = 0; mt < 4; mt++) {
        const int r0 = m0 + wm * 64 + mt * 16 + g;
#pragma unroll
        for (int nb = 0; nb < 4; nb++) {
            const int col = bx * 128 + wn * 32 + nb * 8 + tg * 2;
            float bx0 = 0.f, bx1 = 0.f;
            if (bias) { bx0 = bias[col]; bx1 = bias[col + 1]; }
            *(float2*)(C + (size_t)r0 * ldc + col) =
                make_float2(c[mt][nb][0] + bx0, c[mt][nb][1] + bx1);
            *(float2*)(C + (size_t)(r0 + 8) * ldc + col) =
                make_float2(c[mt][nb][2] + bx0, c[mt][nb][3] + bx1);
        }
    }
}

// ---------------- column L2-norm reciprocals over token dim N --------------
__global__ void colnorm_kernel()
{
    const int b = blockIdx.y;
    const int lane = threadIdx.x & 31;
    const int w = threadIdx.x >> 5;
    const int j = blockIdx.x * 32 + lane;
    const float* p = g_qkv + (size_t)b * N_ * QKV_COLS + j;

    float s0 = 0.f, s1 = 0.f, s2 = 0.f, s3 = 0.f;
    for (int n0 = w * 4; n0 < N_; n0 += 32) {
        float v0 = p[(size_t)(n0 + 0) * QKV_COLS];
        float v1 = p[(size_t)(n0 + 1) * QKV_COLS];
        float v2 = p[(size_t)(n0 + 2) * QKV_COLS];
        float v3 = p[(size_t)(n0 + 3) * QKV_COLS];
        s0 += v0 * v0; s1 += v1 * v1; s2 += v2 * v2; s3 += v3 * v3;
    }
    __shared__ float red[8][32];
    red[w][lane] = (s0 + s1) + (s2 + s3);
    __syncthreads();
    if (w == 0) {
        float t = 0.f;
#pragma unroll
        for (int r = 0; r < 8; r++) t += red[r][lane];
        g_rn[b * (2 * C_) + j] = 1.f / fmaxf(sqrtf(t), 1e-12f);
    }
}

__global__ void zeroS_kernel()
{
    int i = blockIdx.x * blockDim.x + threadIdx.x;
    if (i < B_ * H_ * HD * HD) g_S[i] = 0.f;
}

// ---------------- QK^T partial: per (b,h), split N into 8 chunks -----------
__global__ void __launch_bounds__(256)
attn_partial_kernel()
{
    const int bh = blockIdx.x, b = bh >> 3, h = bh & 7;
    const int chunk = blockIdx.y;
    const int tid = threadIdx.x;
    const int te = tid & 15, td = tid >> 4;

    __shared__ float qs[32][96];
    __shared__ float ks[32][96];

    float acc[6][6];
#pragma unroll
    for (int i = 0; i < 6; i++)
#pragma unroll
        for (int j = 0; j < 6; j++) acc[i][j] = 0.f;

    const size_t base = ((size_t)(b * N_ + chunk * 512)) * QKV_COLS + h * HD;
    for (int t = 0; t < 16; t++) {
#pragma unroll
        for (int l = 0; l < 3; l++) {
            int fid = tid + l * 256;
            int r = fid / 24, cc = fid % 24;
            size_t off = base + (size_t)(t * 32 + r) * QKV_COLS + cc * 4;
            *(float4*)&qs[r][cc * 4] = *(const float4*)(g_qkv + off);
            *(float4*)&ks[r][cc * 4] = *(const float4*)(g_qkv + off + C_);
        }
        __syncthreads();
#pragma unroll 4
        for (int r = 0; r < 32; r++) {
            float a[6], bb[6];
#pragma unroll
            for (int i = 0; i < 6; i++) a[i] = qs[r][td * 6 + i];
#pragma unroll
            for (int j = 0; j < 6; j++) bb[j] = ks[r][te * 6 + j];
#pragma unroll
            for (int i = 0; i < 6; i++)
#pragma unroll
                for (int j = 0; j < 6; j++) acc[i][j] = fmaf(a[i], bb[j], acc[i][j]);
        }
        __syncthreads();
    }
    float* Sp = g_S + (size_t)bh * HD * HD;
#pragma unroll
    for (int i = 0; i < 6; i++)
#pragma unroll
        for (int j = 0; j < 6; j++)
            atomicAdd(&Sp[(td * 6 + i) * HD + te * 6 + j], acc[i][j]);
}

// ---------------- scale by 1/(||q|| ||k||) * temperature, softmax ----------
__global__ void softmax_kernel(const float* __restrict__ temp)
{
    const int bh = blockIdx.x, b = bh >> 3, h = bh & 7;
    const int d = threadIdx.x;
    if (d >= HD) return;
    float* row = g_S + (size_t)bh * HD * HD + d * HD;
    const float rq = g_rn[b * (2 * C_) + h * HD + d] * temp[h];
    const float* rk = g_rn + b * (2 * C_) + C_ + h * HD;

    float vals[HD];
    float m = -1e30f;
    for (int e = 0; e < HD; e++) {
        float v = row[e] * rq * rk[e];
        vals[e] = v;
        if (v > m) m = v;
    }
    float ssum = 0.f;
    for (int e = 0; e < HD; e++) {
        float v = expf(vals[e] - m);
        vals[e] = v;
        ssum += v;
    }
    float inv = 1.f / ssum;
    for (int e = 0; e < HD; e++) row[e] = vals[e] * inv;
}

// ---------------- AV: per (b,h) per 128-token block -------------------------
__global__ void __launch_bounds__(256)
av_kernel()
{
    const int nb = blockIdx.x;
    const int bh = blockIdx.y, b = bh >> 3, h = bh & 7;
    const int tid = threadIdx.x;
    const int tdd = tid & 15, tnn = tid >> 4;

    __shared__ float at[96][100];
    __shared__ float vs[16][132];

    const float* Sp = g_S + (size_t)bh * HD * HD;
#pragma unroll
    for (int l = 0; l < 36; l++) {
        int idx = tid + l * 256;
        int d = idx / 96, e = idx % 96;
        at[e][d] = Sp[idx];
    }

    float acc[8][6];
#pragma unroll
    for (int i = 0; i < 8; i++)
#pragma unroll
        for (int j = 0; j < 6; j++) acc[i][j] = 0.f;

    const size_t basev = ((size_t)(b * N_ + nb * 128)) * QKV_COLS + 2 * C_ + h * HD;
    for (int ec = 0; ec < 6; ec++) {
        __syncthreads();
#pragma unroll
        for (int l = 0; l < 2; l++) {
            int fid = tid + l * 256;
            int r = fid >> 2, cc = fid & 3;
            float4 v = *(const float4*)(g_qkv + basev + (size_t)r * QKV_COLS + ec * 16 + cc * 4);
            vs[cc * 4 + 0][r] = v.x; vs[cc * 4 + 1][r] = v.y;
            vs[cc * 4 + 2][r] = v.z; vs[cc * 4 + 3][r] = v.w;
        }
        __syncthreads();
#pragma unroll
        for (int e = 0; e < 16; e++) {
            float4 va = *(const float4*)&vs[e][tnn * 8];
            float4 vb = *(const float4*)&vs[e][tnn * 8 + 4];
            const float2* wp = (const float2*)&at[ec * 16 + e][tdd * 6];
            float2 w01 = wp[0], w23 = wp[1], w45 = wp[2];
            float a[8] = {va.x, va.y, va.z, va.w, vb.x, vb.y, vb.z, vb.w};
            float w[6] = {w01.x, w01.y, w23.x, w23.y, w45.x, w45.y};
#pragma unroll
            for (int i = 0; i < 8; i++)
#pragma unroll
                for (int j = 0; j < 6; j++) acc[i][j] = fmaf(a[i], w[j], acc[i][j]);
        }
    }

#pragma unroll
    for (int i = 0; i < 8; i++) {
        size_t row = (size_t)(b * N_ + nb * 128 + tnn * 8 + i);
        float* cp = g_ctx + row * C_ + h * HD + tdd * 6;
        *(float2*)(cp + 0) = make_float2(acc[i][0], acc[i][1]);
        *(float2*)(cp + 2) = make_float2(acc[i][2], acc[i][3]);
        *(float2*)(cp + 4) = make_float2(acc[i][4], acc[i][5]);
    }
}

// ---------------- launch ----------------------------------------------------
extern "C" void kernel_launch(void* const* d_in, const int* in_sizes, int n_in,
                              void* d_out, int out_size)
{
    const float* x     = (const float*)d_in[0];
    const float* Wqkv  = (const float*)d_in[1];
    const float* temp  = (const float*)d_in[2];
    const float* Wproj = (const float*)d_in[3];
    const float* bproj = (const float*)d_in[4];
    float* out = (float*)d_out;

    cudaFuncSetAttribute(gemm_bf16_kernel<0, 1>,
                         cudaFuncAttributeMaxDynamicSharedMemorySize, GEMM_DSMEM);
    cudaFuncSetAttribute(gemm_bf16_kernel<1, 0>,
                         cudaFuncAttributeMaxDynamicSharedMemorySize, GEMM_DSMEM);

    // 0) prepack weights + split x into bf16 hi/lo tiles
    prepack_kernel<<<(KDIM * QKV_COLS) / 256, 256>>>(Wqkv, g_Bpk1, QKV_COLS);
    prepack_kernel<<<(KDIM * C_) / 256, 256>>>(Wproj, g_Bpk2, C_);
    asplit_kernel<0><<<(M_ * KDIM / 4) / 256, 256>>>(x);

    // 1) qkv = x @ Wqkv -> g_qkv   (bf16 split-3 mma.sync)
    gemm_bf16_kernel<0, 1><<<dim3(QKV_COLS / 128, M_ / 128), 256, GEMM_DSMEM>>>(
        g_Bpk1, nullptr, nullptr, QKV_COLS);

    // 2) per-(b,channel) reciprocal L2 norms of q and k columns
    colnorm_kernel<<<dim3((2 * C_) / 32, B_), 256>>>();

    // 3) zero logits, then QK^T partial sums
    zeroS_kernel<<<(B_ * H_ * HD * HD + 255) / 256, 256>>>();
    attn_partial_kernel<<<dim3(B_ * H_, 8), 256>>>();

    // 4) scale + softmax
    softmax_kernel<<<B_ * H_, 96>>>(temp);

    // 5) ctx = attn @ v
    av_kernel<<<dim3(32, B_ * H_), 256>>>();

    // 6) split ctx, then out = ctx @ Wproj + bproj
    asplit_kernel<1><<<(M_ * KDIM / 4) / 256, 256>>>(nullptr);
    gemm_bf16_kernel<1, 0><<<dim3(C_ / 128, M_ / 128), 256, GEMM_DSMEM>>>(
        g_Bpk2, out, bproj, C_);
}

// round 5
// speedup vs baseline: 5.3846x; 5.3846x over previous
#include <cuda_runtime.h>
#include <math.h>
#include <stdint.h>

#define B_ 8
#define N_ 4096
#define C_ 768
#define H_ 8
#define HD 96
#define M_ (B_*N_)        // 32768 rows
#define QKV_COLS (3*C_)   // 2304

// ---------------- scratch (device globals: allocation-free) ----------------
__device__ __align__(128) float g_qkv[(size_t)M_ * QKV_COLS];   // [M, 3C]
__device__ __align__(128) float g_ctx[(size_t)M_ * C_];         // [M, C]
__device__ __align__(128) float g_S[B_ * H_ * HD * HD];         // logits/attn
__device__ __align__(128) float g_rn[B_ * 2 * C_];              // 1/max(||col||,eps)

// ---------------- packed fp32x2 helpers (FFMA2 path) ------------------------
typedef unsigned long long u64;
__device__ __forceinline__ u64 pack2(float lo, float hi) {
    u64 r; asm("mov.b64 %0, {%1,%2};" : "=l"(r) : "f"(lo), "f"(hi)); return r;
}
__device__ __forceinline__ void unpack2(u64 v, float& lo, float& hi) {
    asm("mov.b64 {%0,%1}, %2;" : "=f"(lo), "=f"(hi) : "l"(v));
}
__device__ __forceinline__ u64 ffma2(u64 a, u64 b, u64 c) {
    u64 d; asm("fma.rn.f32x2 %0, %1, %2, %3;" : "=l"(d) : "l"(a), "l"(b), "l"(c)); return d;
}

// ---------------- SGEMM v2: 128x128x16, A duplicated+swizzled in SMEM -------
// As[2][16][AP]: dup pairs, col'(m) = 2m + ((m>>4)<<2), pitch AP=292
// Bs[2][16][128]
#define AP 292
#define ABUF (16 * AP)        // floats per A buffer
#define BBUF (16 * 128)
#define GEMM_SMEM ((2 * (ABUF + BBUF)) * 4)

template<bool A_CTX, bool C_QKV>
__global__ void __launch_bounds__(256, 2)
sgemm2_kernel(const float* __restrict__ Ap, const float* __restrict__ Bm,
              float* __restrict__ Cp, const float* __restrict__ bias,
              int Ndim, int K, int ldb, int ldc)
{
    const float* A = A_CTX ? (const float*)g_ctx : Ap;
    float*       C = C_QKV ? (float*)g_qkv : Cp;

    extern __shared__ float sm[];
    float* As = sm;                 // [2][16][AP]
    float* Bs = sm + 2 * ABUF;      // [2][16][128]

    const int tid = threadIdx.x;
    const int tm = tid & 15, tn = tid >> 4;
    const int m0 = blockIdx.y * 128, n0 = blockIdx.x * 128;

    u64 acc[8][4];
#pragma unroll
    for (int i = 0; i < 8; i++)
#pragma unroll
        for (int j = 0; j < 4; j++) acc[i][j] = pack2(0.f, 0.f);

    float4 ra[2], rb[2];

    auto ldg = [&](int kt) {
#pragma unroll
        for (int l = 0; l < 2; l++) {
            int fid = tid + l * 256;
            int ar = fid >> 2, ac = fid & 3;
            ra[l] = *(const float4*)(A + (size_t)(m0 + ar) * K + kt * 16 + ac * 4);
            int br = fid >> 5, bc = fid & 31;
            rb[l] = *(const float4*)(Bm + (size_t)(kt * 16 + br) * ldb + n0 + bc * 4);
        }
    };
    auto sts = [&](int s) {
        float* Ab = As + s * ABUF;
        float* Bb = Bs + s * BBUF;
#pragma unroll
        for (int l = 0; l < 2; l++) {
            int fid = tid + l * 256;
            int ar = fid >> 2, ac = fid & 3;
            int colp = 2 * ar + ((ar >> 4) << 2);     // dup+swizzle column
            float v[4] = {ra[l].x, ra[l].y, ra[l].z, ra[l].w};
#pragma unroll
            for (int q = 0; q < 4; q++)
                *(float2*)&Ab[(ac * 4 + q) * AP + colp] = make_float2(v[q], v[q]);
            int br = fid >> 5, bc = fid & 31;
            *(float4*)&Bb[br * 128 + bc * 4] = rb[l];
        }
    };

    ldg(0);
    sts(0);
    __syncthreads();

    const int KT = K >> 4;
    const int acol = tm * 16 + (tm >> 1) * 4;   // swizzled frag base for this thread
    for (int kt = 0; kt < KT; ++kt) {
        const int s = kt & 1;
        if (kt + 1 < KT) ldg(kt + 1);
        const float* Ab = As + s * ABUF;
        const float* Bb = Bs + s * BBUF;
#pragma unroll
        for (int k = 0; k < 16; k++) {
            const float* ap = Ab + k * AP + acol;
            ulonglong2 a01 = *(const ulonglong2*)(ap);
            ulonglong2 a23 = *(const ulonglong2*)(ap + 4);
            ulonglong2 a45 = *(const ulonglong2*)(ap + 8);
            ulonglong2 a67 = *(const ulonglong2*)(ap + 12);
            const float* bp = Bb + k * 128 + tn * 8;
            ulonglong2 b01 = *(const ulonglong2*)(bp);
            ulonglong2 b23 = *(const ulonglong2*)(bp + 4);
            u64 apk[8] = {a01.x, a01.y, a23.x, a23.y, a45.x, a45.y, a67.x, a67.y};
            u64 bpk[4] = {b01.x, b01.y, b23.x, b23.y};
#pragma unroll
            for (int i = 0; i < 8; i++) {
                acc[i][0] = ffma2(apk[i], bpk[0], acc[i][0]);
                acc[i][1] = ffma2(apk[i], bpk[1], acc[i][1]);
                acc[i][2] = ffma2(apk[i], bpk[2], acc[i][2]);
                acc[i][3] = ffma2(apk[i], bpk[3], acc[i][3]);
            }
        }
        __syncthreads();
        if (kt + 1 < KT) {
            sts(s ^ 1);
            __syncthreads();
        }
    }

    // epilogue
#pragma unroll
    for (int i = 0; i < 8; i++) {
        int row = m0 + tm * 8 + i;
        float* cp = C + (size_t)row * ldc + n0 + tn * 8;
#pragma unroll
        for (int jp = 0; jp < 4; jp++) {
            float lo, hi; unpack2(acc[i][jp], lo, hi);
            if (bias) {
                lo += bias[n0 + tn * 8 + jp * 2];
                hi += bias[n0 + tn * 8 + jp * 2 + 1];
            }
            *(float2*)(cp + jp * 2) = make_float2(lo, hi);
        }
    }
}

// ---------------- column L2-norm reciprocals over token dim N --------------
__global__ void colnorm_kernel()
{
    const int b = blockIdx.y;
    const int lane = threadIdx.x & 31;
    const int w = threadIdx.x >> 5;
    const int j = blockIdx.x * 32 + lane;
    const float* p = g_qkv + (size_t)b * N_ * QKV_COLS + j;

    float s0 = 0.f, s1 = 0.f, s2 = 0.f, s3 = 0.f;
    for (int n0 = w * 4; n0 < N_; n0 += 32) {
        float v0 = p[(size_t)(n0 + 0) * QKV_COLS];
        float v1 = p[(size_t)(n0 + 1) * QKV_COLS];
        float v2 = p[(size_t)(n0 + 2) * QKV_COLS];
        float v3 = p[(size_t)(n0 + 3) * QKV_COLS];
        s0 += v0 * v0; s1 += v1 * v1; s2 += v2 * v2; s3 += v3 * v3;
    }
    __shared__ float red[8][32];
    red[w][lane] = (s0 + s1) + (s2 + s3);
    __syncthreads();
    if (w == 0) {
        float t = 0.f;
#pragma unroll
        for (int r = 0; r < 8; r++) t += red[r][lane];
        g_rn[b * (2 * C_) + j] = 1.f / fmaxf(sqrtf(t), 1e-12f);
    }
}

__global__ void zeroS_kernel()
{
    int i = blockIdx.x * blockDim.x + threadIdx.x;
    if (i < B_ * H_ * HD * HD) g_S[i] = 0.f;
}

// ---------------- QK^T partial: per (b,h), split N into 8 chunks (f32x2) ---
__global__ void __launch_bounds__(256)
attn_partial_kernel()
{
    const int bh = blockIdx.x, b = bh >> 3, h = bh & 7;
    const int chunk = blockIdx.y;
    const int tid = threadIdx.x;
    const int te = tid & 15, td = tid >> 4;

    __shared__ float qs[32][96];
    __shared__ float ks[32][96];

    u64 acc2[6][3];
#pragma unroll
    for (int i = 0; i < 6; i++)
#pragma unroll
        for (int p = 0; p < 3; p++) acc2[i][p] = pack2(0.f, 0.f);

    const size_t base = ((size_t)(b * N_ + chunk * 512)) * QKV_COLS + h * HD;
    for (int t = 0; t < 16; t++) {
#pragma unroll
        for (int l = 0; l < 3; l++) {
            int fid = tid + l * 256;
            int r = fid / 24, cc = fid % 24;
            size_t off = base + (size_t)(t * 32 + r) * QKV_COLS + cc * 4;
            *(float4*)&qs[r][cc * 4] = *(const float4*)(g_qkv + off);
            *(float4*)&ks[r][cc * 4] = *(const float4*)(g_qkv + off + C_);
        }
        __syncthreads();
#pragma unroll 4
        for (int r = 0; r < 32; r++) {
            const u64* bp = (const u64*)&ks[r][te * 6];   // 24B-aligned
            u64 b0 = bp[0], b1 = bp[1], b2 = bp[2];
#pragma unroll
            for (int i = 0; i < 6; i++) {
                float a = qs[r][td * 6 + i];
                u64 ad = pack2(a, a);
                acc2[i][0] = ffma2(ad, b0, acc2[i][0]);
                acc2[i][1] = ffma2(ad, b1, acc2[i][1]);
                acc2[i][2] = ffma2(ad, b2, acc2[i][2]);
            }
        }
        __syncthreads();
    }
    float* Sp = g_S + (size_t)bh * HD * HD;
#pragma unroll
    for (int i = 0; i < 6; i++)
#pragma unroll
        for (int p = 0; p < 3; p++) {
            float lo, hi; unpack2(acc2[i][p], lo, hi);
            atomicAdd(&Sp[(td * 6 + i) * HD + te * 6 + 2 * p], lo);
            atomicAdd(&Sp[(td * 6 + i) * HD + te * 6 + 2 * p + 1], hi);
        }
}

// ---------------- scale by 1/(||q|| ||k||) * temperature, softmax ----------
__global__ void softmax_kernel(const float* __restrict__ temp)
{
    const int bh = blockIdx.x, b = bh >> 3, h = bh & 7;
    const int d = threadIdx.x;
    if (d >= HD) return;
    float* row = g_S + (size_t)bh * HD * HD + d * HD;
    const float rq = g_rn[b * (2 * C_) + h * HD + d] * temp[h];
    const float* rk = g_rn + b * (2 * C_) + C_ + h * HD;

    float vals[HD];
    float m = -1e30f;
    for (int e = 0; e < HD; e++) {
        float v = row[e] * rq * rk[e];
        vals[e] = v;
        if (v > m) m = v;
    }
    float ssum = 0.f;
    for (int e = 0; e < HD; e++) {
        float v = expf(vals[e] - m);
        vals[e] = v;
        ssum += v;
    }
    float inv = 1.f / ssum;
    for (int e = 0; e < HD; e++) row[e] = vals[e] * inv;
}

// ---------------- AV: per (b,h) per 128-token block (f32x2, i-pairs) --------
__global__ void __launch_bounds__(256)
av_kernel()
{
    const int nb = blockIdx.x;
    const int bh = blockIdx.y, b = bh >> 3, h = bh & 7;
    const int tid = threadIdx.x;
    const int tdd = tid & 15, tnn = tid >> 4;

    __shared__ float at[96][100];
    __shared__ float vs[16][132];

    const float* Sp = g_S + (size_t)bh * HD * HD;
#pragma unroll
    for (int l = 0; l < 36; l++) {
        int idx = tid + l * 256;
        int d = idx / 96, e = idx % 96;
        at[e][d] = Sp[idx];
    }

    u64 acc2[4][6];
#pragma unroll
    for (int p = 0; p < 4; p++)
#pragma unroll
        for (int j = 0; j < 6; j++) acc2[p][j] = pack2(0.f, 0.f);

    const size_t basev = ((size_t)(b * N_ + nb * 128)) * QKV_COLS + 2 * C_ + h * HD;
    for (int ec = 0; ec < 6; ec++) {
        __syncthreads();
#pragma unroll
        for (int l = 0; l < 2; l++) {
            int fid = tid + l * 256;
            int r = fid >> 2, cc = fid & 3;
            float4 v = *(const float4*)(g_qkv + basev + (size_t)r * QKV_COLS + ec * 16 + cc * 4);
            vs[cc * 4 + 0][r] = v.x; vs[cc * 4 + 1][r] = v.y;
            vs[cc * 4 + 2][r] = v.z; vs[cc * 4 + 3][r] = v.w;
        }
        __syncthreads();
#pragma unroll
        for (int e = 0; e < 16; e++) {
            const ulonglong2* vp = (const ulonglong2*)&vs[e][tnn * 8];  // 32B-aligned
            ulonglong2 v01 = vp[0], v23 = vp[1];
            u64 vk[4] = {v01.x, v01.y, v23.x, v23.y};    // token pairs (2p,2p+1)
            const float* wp = &at[ec * 16 + e][tdd * 6];
#pragma unroll
            for (int j = 0; j < 6; j++) {
                float w = wp[j];
                u64 wd = pack2(w, w);
                acc2[0][j] = ffma2(vk[0], wd, acc2[0][j]);
                acc2[1][j] = ffma2(vk[1], wd, acc2[1][j]);
                acc2[2][j] = ffma2(vk[2], wd, acc2[2][j]);
                acc2[3][j] = ffma2(vk[3], wd, acc2[3][j]);
            }
        }
    }

#pragma unroll
    for (int p = 0; p < 4; p++) {
        float lo[6], hi[6];
#pragma unroll
        for (int j = 0; j < 6; j++) unpack2(acc2[p][j], lo[j], hi[j]);
        size_t row0 = (size_t)(b * N_ + nb * 128 + tnn * 8 + 2 * p);
        float* cp0 = g_ctx + row0 * C_ + h * HD + tdd * 6;
        float* cp1 = cp0 + C_;
        *(float2*)(cp0 + 0) = make_float2(lo[0], lo[1]);
        *(float2*)(cp0 + 2) = make_float2(lo[2], lo[3]);
        *(float2*)(cp0 + 4) = make_float2(lo[4], lo[5]);
        *(float2*)(cp1 + 0) = make_float2(hi[0], hi[1]);
        *(float2*)(cp1 + 2) = make_float2(hi[2], hi[3]);
        *(float2*)(cp1 + 4) = make_float2(hi[4], hi[5]);
    }
}

// ---------------- launch ----------------------------------------------------
extern "C" void kernel_launch(void* const* d_in, const int* in_sizes, int n_in,
                              void* d_out, int out_size)
{
    const float* x     = (const float*)d_in[0];
    const float* Wqkv  = (const float*)d_in[1];
    const float* temp  = (const float*)d_in[2];
    const float* Wproj = (const float*)d_in[3];
    const float* bproj = (const float*)d_in[4];
    float* out = (float*)d_out;

    cudaFuncSetAttribute(sgemm2_kernel<false, true>,
                         cudaFuncAttributeMaxDynamicSharedMemorySize, GEMM_SMEM);
    cudaFuncSetAttribute(sgemm2_kernel<true, false>,
                         cudaFuncAttributeMaxDynamicSharedMemorySize, GEMM_SMEM);

    // 1) qkv = x @ Wqkv  -> g_qkv [M, 3C]
    sgemm2_kernel<false, true><<<dim3(QKV_COLS / 128, M_ / 128), 256, GEMM_SMEM>>>(
        x, Wqkv, nullptr, nullptr, QKV_COLS, C_, QKV_COLS, QKV_COLS);

    // 2) per-(b,channel) reciprocal L2 norms of q and k columns
    colnorm_kernel<<<dim3((2 * C_) / 32, B_), 256>>>();

    // 3) zero logits, then QK^T partial sums
    zeroS_kernel<<<(B_ * H_ * HD * HD + 255) / 256, 256>>>();
    attn_partial_kernel<<<dim3(B_ * H_, 8), 256>>>();

    // 4) scale + softmax
    softmax_kernel<<<B_ * H_, 96>>>(temp);

    // 5) ctx = attn @ v
    av_kernel<<<dim3(32, B_ * H_), 256>>>();

    // 6) out = ctx @ Wproj + bproj
    sgemm2_kernel<true, false><<<dim3(C_ / 128, M_ / 128), 256, GEMM_SMEM>>>(
        nullptr, Wproj, out, bproj, C_, C_, C_, C_);
}

// round 6
// speedup vs baseline: 7.2163x; 1.3402x over previous
#include <cuda_runtime.h>
#include <math.h>
#include <stdint.h>

#define B_ 8
#define N_ 4096
#define C_ 768
#define H_ 8
#define HD 96
#define M_ (B_*N_)        // 32768 rows
#define QKV_COLS (3*C_)   // 2304

// ---------------- scratch (device globals: allocation-free) ----------------
__device__ __align__(128) float g_G[(size_t)B_ * C_ * C_];        // x^T x per batch
__device__ __align__(128) float g_T[(size_t)B_ * C_ * 2 * C_];    // G @ [Wq|Wk]
__device__ __align__(128) float g_v[(size_t)M_ * C_];             // x @ Wv
__device__ __align__(128) float g_P[(size_t)B_ * C_ * C_];        // attn^T @ Wproj blocks
__device__ __align__(128) float g_S[B_ * H_ * HD * HD];           // logits/attn
__device__ __align__(128) float g_rn[B_ * 2 * C_];                // 1/max(||col||,eps)

// ---------------- packed fp32x2 helpers (FFMA2 path) ------------------------
typedef unsigned long long u64;
__device__ __forceinline__ u64 pack2(float lo, float hi) {
    u64 r; asm("mov.b64 %0, {%1,%2};" : "=l"(r) : "f"(lo), "f"(hi)); return r;
}
__device__ __forceinline__ void unpack2(u64 v, float& lo, float& hi) {
    asm("mov.b64 {%0,%1}, %2;" : "=f"(lo), "=f"(hi) : "l"(v));
}
__device__ __forceinline__ u64 ffma2(u64 a, u64 b, u64 c) {
    u64 d; asm("fma.rn.f32x2 %0, %1, %2, %3;" : "=l"(d) : "l"(a), "l"(b), "l"(c)); return d;
}

// ---------------- generic SGEMM (round-1 proven core, batch-capable) --------
// C[m,n] = sum_k A[m,k] B[k,n] (+bias). Batch via blockIdx.z (A,C) and
// per-4096-row-block batch for B (sBm), used by out = v @ P_b.
__global__ void __launch_bounds__(256, 2)
sgemm_kernel(const float* __restrict__ A, const float* __restrict__ Bm,
             float* __restrict__ C, const float* __restrict__ bias,
             int K, int lda, int ldb, int ldc,
             long long sAz, long long sCz, long long sBm)
{
    const int bz = blockIdx.z;
    const int m0 = blockIdx.y * 128, n0 = blockIdx.x * 128;
    A  += (size_t)bz * sAz;
    C  += (size_t)bz * sCz;
    Bm += (size_t)(m0 >> 12) * sBm;

    __shared__ float As[2][16][128];
    __shared__ float Bs[2][16][128];

    const int tid = threadIdx.x;
    const int tm = tid & 15, tn = tid >> 4;

    u64 acc[8][4];
#pragma unroll
    for (int i = 0; i < 8; i++)
#pragma unroll
        for (int j = 0; j < 4; j++) acc[i][j] = pack2(0.f, 0.f);

    float4 ra[2], rb[2];
#pragma unroll
    for (int l = 0; l < 2; l++) {
        int fid = tid + l * 256;
        int ar = fid >> 2, ac = fid & 3;
        ra[l] = *(const float4*)(A + (size_t)(m0 + ar) * lda + ac * 4);
        int br = fid >> 5, bc = fid & 31;
        rb[l] = *(const float4*)(Bm + (size_t)br * ldb + n0 + bc * 4);
    }
#pragma unroll
    for (int l = 0; l < 2; l++) {
        int fid = tid + l * 256;
        int ar = fid >> 2, ac = fid & 3;
        As[0][ac * 4 + 0][ar] = ra[l].x; As[0][ac * 4 + 1][ar] = ra[l].y;
        As[0][ac * 4 + 2][ar] = ra[l].z; As[0][ac * 4 + 3][ar] = ra[l].w;
        int br = fid >> 5, bc = fid & 31;
        *(float4*)&Bs[0][br][bc * 4] = rb[l];
    }
    __syncthreads();

    const int KT = K >> 4;
    for (int kt = 0; kt < KT; ++kt) {
        const int s = kt & 1;
        if (kt + 1 < KT) {
            int k0 = (kt + 1) << 4;
#pragma unroll
            for (int l = 0; l < 2; l++) {
                int fid = tid + l * 256;
                int ar = fid >> 2, ac = fid & 3;
                ra[l] = *(const float4*)(A + (size_t)(m0 + ar) * lda + k0 + ac * 4);
                int br = fid >> 5, bc = fid & 31;
                rb[l] = *(const float4*)(Bm + (size_t)(k0 + br) * ldb + n0 + bc * 4);
            }
        }
#pragma unroll
        for (int k = 0; k < 16; k++) {
            float4 a0 = *(const float4*)&As[s][k][tm * 8];
            float4 a1 = *(const float4*)&As[s][k][tm * 8 + 4];
            u64 b0 = *(const u64*)&Bs[s][k][tn * 8 + 0];
            u64 b1 = *(const u64*)&Bs[s][k][tn * 8 + 2];
            u64 b2 = *(const u64*)&Bs[s][k][tn * 8 + 4];
            u64 b3 = *(const u64*)&Bs[s][k][tn * 8 + 6];
            float av[8] = {a0.x, a0.y, a0.z, a0.w, a1.x, a1.y, a1.z, a1.w};
#pragma unroll
            for (int i = 0; i < 8; i++) {
                u64 ad = pack2(av[i], av[i]);
                acc[i][0] = ffma2(ad, b0, acc[i][0]);
                acc[i][1] = ffma2(ad, b1, acc[i][1]);
                acc[i][2] = ffma2(ad, b2, acc[i][2]);
                acc[i][3] = ffma2(ad, b3, acc[i][3]);
            }
        }
        __syncthreads();
        if (kt + 1 < KT) {
            const int d = s ^ 1;
#pragma unroll
            for (int l = 0; l < 2; l++) {
                int fid = tid + l * 256;
                int ar = fid >> 2, ac = fid & 3;
                As[d][ac * 4 + 0][ar] = ra[l].x; As[d][ac * 4 + 1][ar] = ra[l].y;
                As[d][ac * 4 + 2][ar] = ra[l].z; As[d][ac * 4 + 3][ar] = ra[l].w;
                int br = fid >> 5, bc = fid & 31;
                *(float4*)&Bs[d][br][bc * 4] = rb[l];
            }
            __syncthreads();
        }
    }

#pragma unroll
    for (int i = 0; i < 8; i++) {
        int row = m0 + tm * 8 + i;
        float* cp = C + (size_t)row * ldc + n0 + tn * 8;
#pragma unroll
        for (int jp = 0; jp < 4; jp++) {
            float lo, hi; unpack2(acc[i][jp], lo, hi);
            if (bias) {
                lo += bias[n0 + tn * 8 + jp * 2];
                hi += bias[n0 + tn * 8 + jp * 2 + 1];
            }
            *(float2*)(cp + jp * 2) = make_float2(lo, hi);
        }
    }
}

// ---------------- zero G -----------------------------------------------------
__global__ void zeroG_kernel()
{
    size_t i = (size_t)blockIdx.x * 256 + threadIdx.x;
    *(float4*)(g_G + i * 4) = make_float4(0.f, 0.f, 0.f, 0.f);
}

// ---------------- Gram: G_b = x_b^T x_b, lower-tri tiles + mirror, k-split 2 -
__global__ void __launch_bounds__(256, 2)
gram_kernel(const float* __restrict__ x)
{
    // decode lower-triangle tile (i >= j) from blockIdx.x in [0,21)
    int i = 0, rem = blockIdx.x;
    while (rem > i) { rem -= i + 1; i++; }
    const int j = rem;
    const int b = blockIdx.y, kz = blockIdx.z;
    const float* xb = x + ((size_t)b * N_ + (size_t)kz * 2048) * C_;

    __shared__ float As[2][16][128];   // [k][m]  (i-block channels)
    __shared__ float Bs[2][16][128];   // [k][n]  (j-block channels)

    const int tid = threadIdx.x;
    const int tm = tid & 15, tn = tid >> 4;

    u64 acc[8][4];
#pragma unroll
    for (int q = 0; q < 8; q++)
#pragma unroll
        for (int p = 0; p < 4; p++) acc[q][p] = pack2(0.f, 0.f);

    float4 ra[2], rb[2];
    const int row_l = tid >> 5, c4 = tid & 31;          // used via fid below

    auto ldg = [&](int kt) {
#pragma unroll
        for (int l = 0; l < 2; l++) {
            int fid = tid + l * 256;
            int r = fid >> 5, cc = fid & 31;
            const float* src = xb + (size_t)(kt * 16 + r) * C_ + cc * 4;
            ra[l] = *(const float4*)(src + i * 128);
            rb[l] = *(const float4*)(src + j * 128);
        }
    };
    auto sts = [&](int s) {
#pragma unroll
        for (int l = 0; l < 2; l++) {
            int fid = tid + l * 256;
            int r = fid >> 5, cc = fid & 31;
            *(float4*)&As[s][r][cc * 4] = ra[l];
            *(float4*)&Bs[s][r][cc * 4] = rb[l];
        }
    };
    (void)row_l; (void)c4;

    ldg(0); sts(0);
    __syncthreads();

    const int KT = 2048 / 16;
    for (int kt = 0; kt < KT; ++kt) {
        const int s = kt & 1;
        if (kt + 1 < KT) ldg(kt + 1);
#pragma unroll
        for (int k = 0; k < 16; k++) {
            float4 a0 = *(const float4*)&As[s][k][tm * 8];
            float4 a1 = *(const float4*)&As[s][k][tm * 8 + 4];
            u64 b0 = *(const u64*)&Bs[s][k][tn * 8 + 0];
            u64 b1 = *(const u64*)&Bs[s][k][tn * 8 + 2];
            u64 b2 = *(const u64*)&Bs[s][k][tn * 8 + 4];
            u64 b3 = *(const u64*)&Bs[s][k][tn * 8 + 6];
            float av[8] = {a0.x, a0.y, a0.z, a0.w, a1.x, a1.y, a1.z, a1.w};
#pragma unroll
            for (int q = 0; q < 8; q++) {
                u64 ad = pack2(av[q], av[q]);
                acc[q][0] = ffma2(ad, b0, acc[q][0]);
                acc[q][1] = ffma2(ad, b1, acc[q][1]);
                acc[q][2] = ffma2(ad, b2, acc[q][2]);
                acc[q][3] = ffma2(ad, b3, acc[q][3]);
            }
        }
        __syncthreads();
        if (kt + 1 < KT) {
            sts(s ^ 1);
            __syncthreads();
        }
    }

    float* Gb = g_G + (size_t)b * C_ * C_;
#pragma unroll
    for (int q = 0; q < 8; q++) {
        int gi = i * 128 + tm * 8 + q;
#pragma unroll
        for (int p = 0; p < 4; p++) {
            float lo, hi; unpack2(acc[q][p], lo, hi);
            int gj = j * 128 + tn * 8 + 2 * p;
            atomicAdd(&Gb[(size_t)gi * C_ + gj], lo);
            atomicAdd(&Gb[(size_t)gi * C_ + gj + 1], hi);
            if (i != j) {
                atomicAdd(&Gb[(size_t)gj * C_ + gi], lo);
                atomicAdd(&Gb[(size_t)(gj + 1) * C_ + gi], hi);
            }
        }
    }
}

// ---------------- diag norms: rn[b,c] = 1/max(sqrt(<W[:,c],T_b[:,c]>),eps) ---
__global__ void diagnorm_kernel(const float* __restrict__ Wqkv)
{
    const int b = blockIdx.y;
    const int lane = threadIdx.x & 31;
    const int w = threadIdx.x >> 5;
    const int c = blockIdx.x * 32 + lane;        // c in [0,1536)
    const float* T = g_T + (size_t)b * C_ * (2 * C_);

    float acc = 0.f;
    for (int r = w; r < C_; r += 8)
        acc += Wqkv[(size_t)r * QKV_COLS + c] * T[(size_t)r * (2 * C_) + c];

    __shared__ float red[8][32];
    red[w][lane] = acc;
    __syncthreads();
    if (w == 0) {
        float t = 0.f;
#pragma unroll
        for (int r = 0; r < 8; r++) t += red[r][lane];
        g_rn[b * (2 * C_) + c] = 1.f / fmaxf(sqrtf(t), 1e-12f);
    }
}

// ---------------- S_bh = Wq_h^T @ Tk_bh  (96x96, K=768) ---------------------
__global__ void __launch_bounds__(256)
s_kernel(const float* __restrict__ Wqkv)
{
    const int bh = blockIdx.x, b = bh >> 3, h = bh & 7;
    const int tid = threadIdx.x;
    const int te = tid & 15, td = tid >> 4;

    __shared__ float qs[32][96];
    __shared__ float ks[32][96];

    u64 acc2[6][3];
#pragma unroll
    for (int q = 0; q < 6; q++)
#pragma unroll
        for (int p = 0; p < 3; p++) acc2[q][p] = pack2(0.f, 0.f);

    const float* Wq = Wqkv + h * HD;                               // col block
    const float* Tk = g_T + (size_t)b * C_ * (2 * C_) + C_ + h * HD;

    for (int t = 0; t < 24; t++) {
#pragma unroll
        for (int l = 0; l < 3; l++) {
            int fid = tid + l * 256;
            int r = fid / 24, cc = fid % 24;
            *(float4*)&qs[r][cc * 4] =
                *(const float4*)(Wq + (size_t)(t * 32 + r) * QKV_COLS + cc * 4);
            *(float4*)&ks[r][cc * 4] =
                *(const float4*)(Tk + (size_t)(t * 32 + r) * (2 * C_) + cc * 4);
        }
        __syncthreads();
#pragma unroll 4
        for (int r = 0; r < 32; r++) {
            const u64* bp = (const u64*)&ks[r][te * 6];
            u64 b0 = bp[0], b1 = bp[1], b2 = bp[2];
#pragma unroll
            for (int q = 0; q < 6; q++) {
                float a = qs[r][td * 6 + q];
                u64 ad = pack2(a, a);
                acc2[q][0] = ffma2(ad, b0, acc2[q][0]);
                acc2[q][1] = ffma2(ad, b1, acc2[q][1]);
                acc2[q][2] = ffma2(ad, b2, acc2[q][2]);
            }
        }
        __syncthreads();
    }
    float* Sp = g_S + (size_t)bh * HD * HD;
#pragma unroll
    for (int q = 0; q < 6; q++)
#pragma unroll
        for (int p = 0; p < 3; p++) {
            float lo, hi; unpack2(acc2[q][p], lo, hi);
            *(float2*)&Sp[(td * 6 + q) * HD + te * 6 + 2 * p] = make_float2(lo, hi);
        }
}

// ---------------- scale + softmax (in place in g_S) --------------------------
__global__ void softmax_kernel(const float* __restrict__ temp)
{
    const int bh = blockIdx.x, b = bh >> 3, h = bh & 7;
    const int d = threadIdx.x;
    if (d >= HD) return;
    float* row = g_S + (size_t)bh * HD * HD + d * HD;
    const float rq = g_rn[b * (2 * C_) + h * HD + d] * temp[h];
    const float* rk = g_rn + b * (2 * C_) + C_ + h * HD;

    float vals[HD];
    float m = -1e30f;
    for (int e = 0; e < HD; e++) {
        float v = row[e] * rq * rk[e];
        vals[e] = v;
        if (v > m) m = v;
    }
    float ssum = 0.f;
    for (int e = 0; e < HD; e++) {
        float v = expf(vals[e] - m);
        vals[e] = v;
        ssum += v;
    }
    float inv = 1.f / ssum;
    for (int e = 0; e < HD; e++) row[e] = vals[e] * inv;
}

// ---------------- P_b[h*96+e, j] = sum_d attn_bh[d,e] * Wproj[h*96+d, j] -----
__global__ void __launch_bounds__(256)
p_kernel(const float* __restrict__ Wproj)
{
    const int bh = blockIdx.x, b = bh >> 3, h = bh & 7;
    const int jt = blockIdx.y;
    const int tid = threadIdx.x;
    const int er = tid >> 5, lane = tid & 31;

    __shared__ float ats[32][96];    // attn chunk [d][e]
    __shared__ float ws[32][128];    // Wproj chunk [d][j]

    u64 acc2[12][2];
#pragma unroll
    for (int q = 0; q < 12; q++) { acc2[q][0] = pack2(0.f, 0.f); acc2[q][1] = pack2(0.f, 0.f); }

    const float* Sp = g_S + (size_t)bh * HD * HD;
    const float* Wp = Wproj + (size_t)(h * HD) * C_ + jt * 128;

    for (int dc = 0; dc < 3; dc++) {
        __syncthreads();
#pragma unroll
        for (int l = 0; l < 3; l++) {
            int fid = tid + l * 256;
            int r = fid / 24, cc = fid % 24;
            *(float4*)&ats[r][cc * 4] = *(const float4*)(Sp + (size_t)(dc * 32 + r) * HD + cc * 4);
        }
#pragma unroll
        for (int l = 0; l < 4; l++) {
            int fid = tid + l * 256;
            int r = fid >> 5, cc = fid & 31;
            *(float4*)&ws[r][cc * 4] = *(const float4*)(Wp + (size_t)(dc * 32 + r) * C_ + cc * 4);
        }
        __syncthreads();
#pragma unroll 4
        for (int d = 0; d < 32; d++) {
            u64 w01 = *(const u64*)&ws[d][lane * 4];
            u64 w23 = *(const u64*)&ws[d][lane * 4 + 2];
#pragma unroll
            for (int q = 0; q < 12; q++) {
                float a = ats[d][er * 12 + q];
                u64 ad = pack2(a, a);
                acc2[q][0] = ffma2(ad, w01, acc2[q][0]);
                acc2[q][1] = ffma2(ad, w23, acc2[q][1]);
            }
        }
    }

    float* Pb = g_P + (size_t)b * C_ * C_;
#pragma unroll
    for (int q = 0; q < 12; q++) {
        float f0, f1, f2, f3;
        unpack2(acc2[q][0], f0, f1);
        unpack2(acc2[q][1], f2, f3);
        *(float4*)&Pb[(size_t)(h * HD + er * 12 + q) * C_ + jt * 128 + lane * 4] =
            make_float4(f0, f1, f2, f3);
    }
}

// ---------------- launch ----------------------------------------------------
extern "C" void kernel_launch(void* const* d_in, const int* in_sizes, int n_in,
                              void* d_out, int out_size)
{
    const float* x     = (const float*)d_in[0];
    const float* Wqkv  = (const float*)d_in[1];
    const float* temp  = (const float*)d_in[2];
    const float* Wproj = (const float*)d_in[3];
    const float* bproj = (const float*)d_in[4];
    float* out = (float*)d_out;

    float* Gp = nullptr; float* Tp = nullptr; float* vp = nullptr; float* Pp = nullptr;
    // device-global addresses are linked symbols; take them via kernels directly.

    // 1) zero G, then G_b = x_b^T x_b (lower tiles + mirror, k-split 2)
    zeroG_kernel<<<(B_ * C_ * C_) / (256 * 4), 256>>>();
    gram_kernel<<<dim3(21, B_, 2), 256>>>(x);

    // 2) v = x @ Wv  -> g_v
    {
        void* args_unused = nullptr; (void)args_unused;
    }
    // sgemm needs raw pointers to device globals; pass via separate kernel launches
    // using cudaGetSymbolAddress is allocation-free and capture-safe? It is a
    // synchronous query; do it once via statics.
    static float *dG = nullptr, *dT = nullptr, *dV = nullptr, *dP = nullptr;
    if (!dG) {
        cudaGetSymbolAddress((void**)&dG, g_G);
        cudaGetSymbolAddress((void**)&dT, g_T);
        cudaGetSymbolAddress((void**)&dV, g_v);
        cudaGetSymbolAddress((void**)&dP, g_P);
    }
    (void)Gp; (void)Tp; (void)vp; (void)Pp;

    sgemm_kernel<<<dim3(C_ / 128, M_ / 128, 1), 256>>>(
        x, Wqkv + 2 * C_, dV, nullptr, C_, C_, QKV_COLS, C_, 0, 0, 0);

    // 3) T_b = G_b @ [Wq|Wk]  (first 1536 cols of Wqkv)
    sgemm_kernel<<<dim3((2 * C_) / 128, C_ / 128, B_), 256>>>(
        dG, Wqkv, dT, nullptr, C_, C_, QKV_COLS, 2 * C_,
        (long long)C_ * C_, (long long)C_ * 2 * C_, 0);

    // 4) reciprocal norms from diag(W^T T)
    diagnorm_kernel<<<dim3((2 * C_) / 32, B_), 256>>>(Wqkv);

    // 5) S_bh = Wq_h^T Tk_bh, then softmax
    s_kernel<<<B_ * H_, 256>>>(Wqkv);
    softmax_kernel<<<B_ * H_, 96>>>(temp);

    // 6) P_b = attn^T-blocks @ Wproj
    p_kernel<<<dim3(B_ * H_, C_ / 128), 256>>>(Wproj);

    // 7) out = v @ P_b + bproj  (B selected per 4096-row batch block)
    sgemm_kernel<<<dim3(C_ / 128, M_ / 128, 1), 256>>>(
        dV, dP, out, bproj, C_, C_, C_, C_, 0, 0, (long long)C_ * C_);
}

// round 7
// speedup vs baseline: 10.0674x; 1.3951x over previous
#include <cuda_runtime.h>
#include <math.h>
#include <stdint.h>

#define B_ 8
#define N_ 4096
#define C_ 768
#define H_ 8
#define HD 96
#define M_ (B_*N_)        // 32768 rows
#define QKV_COLS (3*C_)   // 2304

// ---------------- scratch (device globals: allocation-free) ----------------
__device__ __align__(128) float g_G[(size_t)B_ * C_ * C_];        // x^T x per batch
__device__ __align__(128) float g_T[(size_t)B_ * C_ * 2 * C_];    // G @ [Wq|Wk]
__device__ __align__(128) float g_P[(size_t)B_ * C_ * C_];        // attn^T @ Wproj
__device__ __align__(128) float g_Q[(size_t)B_ * C_ * C_];        // Wv @ P_b
__device__ __align__(128) float g_S[B_ * H_ * HD * HD];           // logits/attn
__device__ __align__(128) float g_rn[B_ * 2 * C_];                // 1/max(||col||,eps)

// ---------------- packed fp32x2 helpers (FFMA2 path) ------------------------
typedef unsigned long long u64;
__device__ __forceinline__ u64 pack2(float lo, float hi) {
    u64 r; asm("mov.b64 %0, {%1,%2};" : "=l"(r) : "f"(lo), "f"(hi)); return r;
}
__device__ __forceinline__ void unpack2(u64 v, float& lo, float& hi) {
    asm("mov.b64 {%0,%1}, %2;" : "=f"(lo), "=f"(hi) : "l"(v));
}
__device__ __forceinline__ u64 ffma2(u64 a, u64 b, u64 c) {
    u64 d; asm("fma.rn.f32x2 %0, %1, %2, %3;" : "=l"(d) : "l"(a), "l"(b), "l"(c)); return d;
}

// ---------------- generic SGEMM (proven core, batch-capable) ----------------
// C[m,n] = sum_k A[m,k] B[k,n] (+bias).
// blockIdx.z batching: A += bz*sAz, C += bz*sCz, B += bz*sBz.
// Additionally B += (m0>>12)*sBm  (per-4096-row-block B selection).
__global__ void __launch_bounds__(256, 2)
sgemm_kernel(const float* __restrict__ A, const float* __restrict__ Bm,
             float* __restrict__ C, const float* __restrict__ bias,
             int K, int lda, int ldb, int ldc,
             long long sAz, long long sCz, long long sBz, long long sBm)
{
    const int bz = blockIdx.z;
    const int m0 = blockIdx.y * 128, n0 = blockIdx.x * 128;
    A  += (size_t)bz * sAz;
    C  += (size_t)bz * sCz;
    Bm += (size_t)bz * sBz + (size_t)(m0 >> 12) * sBm;

    __shared__ float As[2][16][128];
    __shared__ float Bs[2][16][128];

    const int tid = threadIdx.x;
    const int tm = tid & 15, tn = tid >> 4;

    u64 acc[8][4];
#pragma unroll
    for (int i = 0; i < 8; i++)
#pragma unroll
        for (int j = 0; j < 4; j++) acc[i][j] = pack2(0.f, 0.f);

    float4 ra[2], rb[2];
#pragma unroll
    for (int l = 0; l < 2; l++) {
        int fid = tid + l * 256;
        int ar = fid >> 2, ac = fid & 3;
        ra[l] = *(const float4*)(A + (size_t)(m0 + ar) * lda + ac * 4);
        int br = fid >> 5, bc = fid & 31;
        rb[l] = *(const float4*)(Bm + (size_t)br * ldb + n0 + bc * 4);
    }
#pragma unroll
    for (int l = 0; l < 2; l++) {
        int fid = tid + l * 256;
        int ar = fid >> 2, ac = fid & 3;
        As[0][ac * 4 + 0][ar] = ra[l].x; As[0][ac * 4 + 1][ar] = ra[l].y;
        As[0][ac * 4 + 2][ar] = ra[l].z; As[0][ac * 4 + 3][ar] = ra[l].w;
        int br = fid >> 5, bc = fid & 31;
        *(float4*)&Bs[0][br][bc * 4] = rb[l];
    }
    __syncthreads();

    const int KT = K >> 4;
    for (int kt = 0; kt < KT; ++kt) {
        const int s = kt & 1;
        if (kt + 1 < KT) {
            int k0 = (kt + 1) << 4;
#pragma unroll
            for (int l = 0; l < 2; l++) {
                int fid = tid + l * 256;
                int ar = fid >> 2, ac = fid & 3;
                ra[l] = *(const float4*)(A + (size_t)(m0 + ar) * lda + k0 + ac * 4);
                int br = fid >> 5, bc = fid & 31;
                rb[l] = *(const float4*)(Bm + (size_t)(k0 + br) * ldb + n0 + bc * 4);
            }
        }
#pragma unroll
        for (int k = 0; k < 16; k++) {
            float4 a0 = *(const float4*)&As[s][k][tm * 8];
            float4 a1 = *(const float4*)&As[s][k][tm * 8 + 4];
            u64 b0 = *(const u64*)&Bs[s][k][tn * 8 + 0];
            u64 b1 = *(const u64*)&Bs[s][k][tn * 8 + 2];
            u64 b2 = *(const u64*)&Bs[s][k][tn * 8 + 4];
            u64 b3 = *(const u64*)&Bs[s][k][tn * 8 + 6];
            float av[8] = {a0.x, a0.y, a0.z, a0.w, a1.x, a1.y, a1.z, a1.w};
#pragma unroll
            for (int i = 0; i < 8; i++) {
                u64 ad = pack2(av[i], av[i]);
                acc[i][0] = ffma2(ad, b0, acc[i][0]);
                acc[i][1] = ffma2(ad, b1, acc[i][1]);
                acc[i][2] = ffma2(ad, b2, acc[i][2]);
                acc[i][3] = ffma2(ad, b3, acc[i][3]);
            }
        }
        __syncthreads();
        if (kt + 1 < KT) {
            const int d = s ^ 1;
#pragma unroll
            for (int l = 0; l < 2; l++) {
                int fid = tid + l * 256;
                int ar = fid >> 2, ac = fid & 3;
                As[d][ac * 4 + 0][ar] = ra[l].x; As[d][ac * 4 + 1][ar] = ra[l].y;
                As[d][ac * 4 + 2][ar] = ra[l].z; As[d][ac * 4 + 3][ar] = ra[l].w;
                int br = fid >> 5, bc = fid & 31;
                *(float4*)&Bs[d][br][bc * 4] = rb[l];
            }
            __syncthreads();
        }
    }

#pragma unroll
    for (int i = 0; i < 8; i++) {
        int row = m0 + tm * 8 + i;
        float* cp = C + (size_t)row * ldc + n0 + tn * 8;
#pragma unroll
        for (int jp = 0; jp < 4; jp++) {
            float lo, hi; unpack2(acc[i][jp], lo, hi);
            if (bias) {
                lo += bias[n0 + tn * 8 + jp * 2];
                hi += bias[n0 + tn * 8 + jp * 2 + 1];
            }
            *(float2*)(cp + jp * 2) = make_float2(lo, hi);
        }
    }
}

// ---------------- zero G -----------------------------------------------------
__global__ void zeroG_kernel()
{
    size_t i = (size_t)blockIdx.x * 256 + threadIdx.x;
    *(float4*)(g_G + i * 4) = make_float4(0.f, 0.f, 0.f, 0.f);
}

// ---------------- Gram: G_b = x_b^T x_b, lower-tri tiles + mirror, k-split 4 -
#define GRAM_KSPLIT 4
#define GRAM_KLEN (N_ / GRAM_KSPLIT)

__global__ void __launch_bounds__(256, 2)
gram_kernel(const float* __restrict__ x)
{
    // decode lower-triangle tile (i >= j) from blockIdx.x in [0,21)
    int i = 0, rem = blockIdx.x;
    while (rem > i) { rem -= i + 1; i++; }
    const int j = rem;
    const int b = blockIdx.y, kz = blockIdx.z;
    const float* xb = x + ((size_t)b * N_ + (size_t)kz * GRAM_KLEN) * C_;

    __shared__ float As[2][16][128];   // [k][m]  (i-block channels)
    __shared__ float Bs[2][16][128];   // [k][n]  (j-block channels)

    const int tid = threadIdx.x;
    const int tm = tid & 15, tn = tid >> 4;

    u64 acc[8][4];
#pragma unroll
    for (int q = 0; q < 8; q++)
#pragma unroll
        for (int p = 0; p < 4; p++) acc[q][p] = pack2(0.f, 0.f);

    float4 ra[2], rb[2];

    auto ldg = [&](int kt) {
#pragma unroll
        for (int l = 0; l < 2; l++) {
            int fid = tid + l * 256;
            int r = fid >> 5, cc = fid & 31;
            const float* src = xb + (size_t)(kt * 16 + r) * C_ + cc * 4;
            ra[l] = *(const float4*)(src + i * 128);
            rb[l] = *(const float4*)(src + j * 128);
        }
    };
    auto sts = [&](int s) {
#pragma unroll
        for (int l = 0; l < 2; l++) {
            int fid = tid + l * 256;
            int r = fid >> 5, cc = fid & 31;
            *(float4*)&As[s][r][cc * 4] = ra[l];
            *(float4*)&Bs[s][r][cc * 4] = rb[l];
        }
    };

    ldg(0); sts(0);
    __syncthreads();

    const int KT = GRAM_KLEN / 16;
    for (int kt = 0; kt < KT; ++kt) {
        const int s = kt & 1;
        if (kt + 1 < KT) ldg(kt + 1);
#pragma unroll
        for (int k = 0; k < 16; k++) {
            float4 a0 = *(const float4*)&As[s][k][tm * 8];
            float4 a1 = *(const float4*)&As[s][k][tm * 8 + 4];
            u64 b0 = *(const u64*)&Bs[s][k][tn * 8 + 0];
            u64 b1 = *(const u64*)&Bs[s][k][tn * 8 + 2];
            u64 b2 = *(const u64*)&Bs[s][k][tn * 8 + 4];
            u64 b3 = *(const u64*)&Bs[s][k][tn * 8 + 6];
            float av[8] = {a0.x, a0.y, a0.z, a0.w, a1.x, a1.y, a1.z, a1.w};
#pragma unroll
            for (int q = 0; q < 8; q++) {
                u64 ad = pack2(av[q], av[q]);
                acc[q][0] = ffma2(ad, b0, acc[q][0]);
                acc[q][1] = ffma2(ad, b1, acc[q][1]);
                acc[q][2] = ffma2(ad, b2, acc[q][2]);
                acc[q][3] = ffma2(ad, b3, acc[q][3]);
            }
        }
        __syncthreads();
        if (kt + 1 < KT) {
            sts(s ^ 1);
            __syncthreads();
        }
    }

    float* Gb = g_G + (size_t)b * C_ * C_;
#pragma unroll
    for (int q = 0; q < 8; q++) {
        int gi = i * 128 + tm * 8 + q;
#pragma unroll
        for (int p = 0; p < 4; p++) {
            float lo, hi; unpack2(acc[q][p], lo, hi);
            int gj = j * 128 + tn * 8 + 2 * p;
            atomicAdd(&Gb[(size_t)gi * C_ + gj], lo);
            atomicAdd(&Gb[(size_t)gi * C_ + gj + 1], hi);
            if (i != j) {
                atomicAdd(&Gb[(size_t)gj * C_ + gi], lo);
                atomicAdd(&Gb[(size_t)(gj + 1) * C_ + gi], hi);
            }
        }
    }
}

// ---------------- diag norms: rn[b,c] = 1/max(sqrt(<W[:,c],T_b[:,c]>),eps) ---
__global__ void diagnorm_kernel(const float* __restrict__ Wqkv)
{
    const int b = blockIdx.y;
    const int lane = threadIdx.x & 31;
    const int w = threadIdx.x >> 5;
    const int c = blockIdx.x * 32 + lane;        // c in [0,1536)
    const float* T = g_T + (size_t)b * C_ * (2 * C_);

    float acc = 0.f;
    for (int r = w; r < C_; r += 8)
        acc += Wqkv[(size_t)r * QKV_COLS + c] * T[(size_t)r * (2 * C_) + c];

    __shared__ float red[8][32];
    red[w][lane] = acc;
    __syncthreads();
    if (w == 0) {
        float t = 0.f;
#pragma unroll
        for (int r = 0; r < 8; r++) t += red[r][lane];
        g_rn[b * (2 * C_) + c] = 1.f / fmaxf(sqrtf(t), 1e-12f);
    }
}

// ---------------- S_bh = Wq_h^T @ Tk_bh  (96x96, K=768) ---------------------
__global__ void __launch_bounds__(256)
s_kernel(const float* __restrict__ Wqkv)
{
    const int bh = blockIdx.x, b = bh >> 3, h = bh & 7;
    const int tid = threadIdx.x;
    const int te = tid & 15, td = tid >> 4;

    __shared__ float qs[32][96];
    __shared__ float ks[32][96];

    u64 acc2[6][3];
#pragma unroll
    for (int q = 0; q < 6; q++)
#pragma unroll
        for (int p = 0; p < 3; p++) acc2[q][p] = pack2(0.f, 0.f);

    const float* Wq = Wqkv + h * HD;
    const float* Tk = g_T + (size_t)b * C_ * (2 * C_) + C_ + h * HD;

    for (int t = 0; t < 24; t++) {
#pragma unroll
        for (int l = 0; l < 3; l++) {
            int fid = tid + l * 256;
            int r = fid / 24, cc = fid % 24;
            *(float4*)&qs[r][cc * 4] =
                *(const float4*)(Wq + (size_t)(t * 32 + r) * QKV_COLS + cc * 4);
            *(float4*)&ks[r][cc * 4] =
                *(const float4*)(Tk + (size_t)(t * 32 + r) * (2 * C_) + cc * 4);
        }
        __syncthreads();
#pragma unroll 4
        for (int r = 0; r < 32; r++) {
            const u64* bp = (const u64*)&ks[r][te * 6];
            u64 b0 = bp[0], b1 = bp[1], b2 = bp[2];
#pragma unroll
            for (int q = 0; q < 6; q++) {
                float a = qs[r][td * 6 + q];
                u64 ad = pack2(a, a);
                acc2[q][0] = ffma2(ad, b0, acc2[q][0]);
                acc2[q][1] = ffma2(ad, b1, acc2[q][1]);
                acc2[q][2] = ffma2(ad, b2, acc2[q][2]);
            }
        }
        __syncthreads();
    }
    float* Sp = g_S + (size_t)bh * HD * HD;
#pragma unroll
    for (int q = 0; q < 6; q++)
#pragma unroll
        for (int p = 0; p < 3; p++) {
            float lo, hi; unpack2(acc2[q][p], lo, hi);
            *(float2*)&Sp[(td * 6 + q) * HD + te * 6 + 2 * p] = make_float2(lo, hi);
        }
}

// ---------------- scale + softmax (in place in g_S) --------------------------
__global__ void softmax_kernel(const float* __restrict__ temp)
{
    const int bh = blockIdx.x, b = bh >> 3, h = bh & 7;
    const int d = threadIdx.x;
    if (d >= HD) return;
    float* row = g_S + (size_t)bh * HD * HD + d * HD;
    const float rq = g_rn[b * (2 * C_) + h * HD + d] * temp[h];
    const float* rk = g_rn + b * (2 * C_) + C_ + h * HD;

    float vals[HD];
    float m = -1e30f;
    for (int e = 0; e < HD; e++) {
        float v = row[e] * rq * rk[e];
        vals[e] = v;
        if (v > m) m = v;
    }
    float ssum = 0.f;
    for (int e = 0; e < HD; e++) {
        float v = expf(vals[e] - m);
        vals[e] = v;
        ssum += v;
    }
    float inv = 1.f / ssum;
    for (int e = 0; e < HD; e++) row[e] = vals[e] * inv;
}

// ---------------- P_b[h*96+e, j] = sum_d attn_bh[d,e] * Wproj[h*96+d, j] -----
__global__ void __launch_bounds__(256)
p_kernel(const float* __restrict__ Wproj)
{
    const int bh = blockIdx.x, b = bh >> 3, h = bh & 7;
    const int jt = blockIdx.y;
    const int tid = threadIdx.x;
    const int er = tid >> 5, lane = tid & 31;

    __shared__ float ats[32][96];    // attn chunk [d][e]
    __shared__ float ws[32][128];    // Wproj chunk [d][j]

    u64 acc2[12][2];
#pragma unroll
    for (int q = 0; q < 12; q++) { acc2[q][0] = pack2(0.f, 0.f); acc2[q][1] = pack2(0.f, 0.f); }

    const float* Sp = g_S + (size_t)bh * HD * HD;
    const float* Wp = Wproj + (size_t)(h * HD) * C_ + jt * 128;

    for (int dc = 0; dc < 3; dc++) {
        __syncthreads();
#pragma unroll
        for (int l = 0; l < 3; l++) {
            int fid = tid + l * 256;
            int r = fid / 24, cc = fid % 24;
            *(float4*)&ats[r][cc * 4] = *(const float4*)(Sp + (size_t)(dc * 32 + r) * HD + cc * 4);
        }
#pragma unroll
        for (int l = 0; l < 4; l++) {
            int fid = tid + l * 256;
            int r = fid >> 5, cc = fid & 31;
            *(float4*)&ws[r][cc * 4] = *(const float4*)(Wp + (size_t)(dc * 32 + r) * C_ + cc * 4);
        }
        __syncthreads();
#pragma unroll 4
        for (int d = 0; d < 32; d++) {
            u64 w01 = *(const u64*)&ws[d][lane * 4];
            u64 w23 = *(const u64*)&ws[d][lane * 4 + 2];
#pragma unroll
            for (int q = 0; q < 12; q++) {
                float a = ats[d][er * 12 + q];
                u64 ad = pack2(a, a);
                acc2[q][0] = ffma2(ad, w01, acc2[q][0]);
                acc2[q][1] = ffma2(ad, w23, acc2[q][1]);
            }
        }
    }

    float* Pb = g_P + (size_t)b * C_ * C_;
#pragma unroll
    for (int q = 0; q < 12; q++) {
        float f0, f1, f2, f3;
        unpack2(acc2[q][0], f0, f1);
        unpack2(acc2[q][1], f2, f3);
        *(float4*)&Pb[(size_t)(h * HD + er * 12 + q) * C_ + jt * 128 + lane * 4] =
            make_float4(f0, f1, f2, f3);
    }
}

// ---------------- launch ----------------------------------------------------
extern "C" void kernel_launch(void* const* d_in, const int* in_sizes, int n_in,
                              void* d_out, int out_size)
{
    const float* x     = (const float*)d_in[0];
    const float* Wqkv  = (const float*)d_in[1];
    const float* temp  = (const float*)d_in[2];
    const float* Wproj = (const float*)d_in[3];
    const float* bproj = (const float*)d_in[4];
    float* out = (float*)d_out;

    static float *dG = nullptr, *dT = nullptr, *dP = nullptr, *dQ = nullptr;
    if (!dG) {
        cudaGetSymbolAddress((void**)&dG, g_G);
        cudaGetSymbolAddress((void**)&dT, g_T);
        cudaGetSymbolAddress((void**)&dP, g_P);
        cudaGetSymbolAddress((void**)&dQ, g_Q);
    }

    // 1) zero G, then G_b = x_b^T x_b (lower tiles + mirror, k-split 4)
    zeroG_kernel<<<(B_ * C_ * C_) / (256 * 4), 256>>>();
    gram_kernel<<<dim3(21, B_, GRAM_KSPLIT), 256>>>(x);

    // 2) T_b = G_b @ [Wq|Wk]  (first 1536 cols of Wqkv)
    sgemm_kernel<<<dim3((2 * C_) / 128, C_ / 128, B_), 256>>>(
        dG, Wqkv, dT, nullptr, C_, C_, QKV_COLS, 2 * C_,
        (long long)C_ * C_, (long long)C_ * 2 * C_, 0, 0);

    // 3) reciprocal norms from diag(W^T T)
    diagnorm_kernel<<<dim3((2 * C_) / 32, B_), 256>>>(Wqkv);

    // 4) S_bh = Wq_h^T Tk_bh, then softmax
    s_kernel<<<B_ * H_, 256>>>(Wqkv);
    softmax_kernel<<<B_ * H_, 96>>>(temp);

    // 5) P_b = attn^T-blocks @ Wproj
    p_kernel<<<dim3(B_ * H_, C_ / 128), 256>>>(Wproj);

    // 6) Q_b = Wv @ P_b   (batched over B; Wv = cols [2C,3C) of Wqkv)
    sgemm_kernel<<<dim3(C_ / 128, C_ / 128, B_), 256>>>(
        Wqkv + 2 * C_, dP, dQ, nullptr, C_, QKV_COLS, C_, C_,
        0, (long long)C_ * C_, (long long)C_ * C_, 0);

    // 7) out = x @ Q_b + bproj  (Q selected per 4096-row batch block)
    sgemm_kernel<<<dim3(C_ / 128, M_ / 128, 1), 256>>>(
        x, dQ, out, bproj, C_, C_, C_, C_, 0, 0, 0, (long long)C_ * C_);
}